// round 12
// baseline (speedup 1.0000x reference)
#include <cuda_runtime.h>
#include <cuda_bf16.h>
#include <cstdint>
#include <math.h>

#define NN 100000
#define EE 3200000
#define FF 128

// ---------------- static device scratch (no allocations allowed) ----------------
__device__ __nv_bfloat16 g_xb[NN * FF];   // bf16 gather source (x, then h1*outnorm)
__device__ __nv_bfloat16 g_aggb[NN * FF]; // bf16 aggregation output
__device__ __nv_bfloat16 g_hb[NN * FF];   // conv2 output
__device__ __nv_bfloat16 g_mb[NN * FF];   // mlp hidden
__device__ __nv_bfloat16 g_w1t[FF * FF];  // W1^T bf16 [n][k]
__device__ __nv_bfloat16 g_w2t[FF * FF];
__device__ __nv_bfloat16 g_wm1t[FF * FF];
__device__ __nv_bfloat16 g_wm2t[64 * FF];
__device__ float g_outnorm[NN];
__device__ float g_innorm[NN];
__device__ int   g_outdeg[NN];
__device__ int   g_indeg[NN];
__device__ int   g_rowptr[NN + 1];
__device__ int   g_cursor[NN];
__device__ int   g_partial[128];
__device__ int   g_csrc[EE];              // CSR (by dst) column indices = src nodes

// ---------------- prep: zero counters + weight transpose/bf16 + x->bf16 ----------------
__global__ void __launch_bounds__(256) prep_kernel(
    const float4* __restrict__ x,
    const float* __restrict__ W1, const float* __restrict__ W2,
    const float* __restrict__ Wm1, const float* __restrict__ Wm2) {
    int i = blockIdx.x * blockDim.x + threadIdx.x;
    if (i < NN) { g_outdeg[i] = 0; g_indeg[i] = 0; }
    if (i < 16384) {
        int k = i >> 7, n = i & 127;
        g_w1t[n * 128 + k] = __float2bfloat16(W1[i]);
        g_w2t[n * 128 + k] = __float2bfloat16(W2[i]);
        g_wm1t[n * 128 + k] = __float2bfloat16(Wm1[i]);
        if (i < 8192) {
            int k2 = i >> 6, n2 = i & 63;
            g_wm2t[n2 * 128 + k2] = __float2bfloat16(Wm2[i]);
        }
    }
    if (i < NN * 32) {
        float4 v = x[i];
        __nv_bfloat162 b0 = __floats2bfloat162_rn(v.x, v.y);
        __nv_bfloat162 b1 = __floats2bfloat162_rn(v.z, v.w);
        uint2 p;
        p.x = *reinterpret_cast<unsigned*>(&b0);
        p.y = *reinterpret_cast<unsigned*>(&b1);
        ((uint2*)g_xb)[i] = p;
    }
}

// ---------------- graph preprocessing ----------------
// 4 edges per thread (EE divisible by 4)
__global__ void __launch_bounds__(256) degree_kernel(const int4* __restrict__ src4, const int4* __restrict__ dst4) {
    int i = blockIdx.x * blockDim.x + threadIdx.x;
    if (i < EE / 4) {
        int4 s = src4[i], d = dst4[i];
        atomicAdd(&g_outdeg[s.x], 1); atomicAdd(&g_outdeg[s.y], 1);
        atomicAdd(&g_outdeg[s.z], 1); atomicAdd(&g_outdeg[s.w], 1);
        atomicAdd(&g_indeg[d.x], 1); atomicAdd(&g_indeg[d.y], 1);
        atomicAdd(&g_indeg[d.z], 1); atomicAdd(&g_indeg[d.w], 1);
    }
}

__global__ void __launch_bounds__(256) scan_reduce_kernel() {
    __shared__ int s[256];
    int t = threadIdx.x;
    int base = blockIdx.x * 1024;
    int v = 0;
#pragma unroll
    for (int j = 0; j < 4; j++) {
        int i = base + t + j * 256;
        if (i < NN) v += g_indeg[i];
    }
    s[t] = v;
    __syncthreads();
    for (int off = 128; off > 0; off >>= 1) {
        if (t < off) s[t] += s[t + off];
        __syncthreads();
    }
    if (t == 0) g_partial[blockIdx.x] = s[0];
}

// downsweep: inline exclusive scan of partials + block-local scan -> rowptr, cursor, norms
__global__ void __launch_bounds__(1024) scan_down_kernel(int nparts) {
    __shared__ int part[128];
    __shared__ int orig[128];
    __shared__ int s[1024];
    int t = threadIdx.x;
    if (t < 128) {
        int v = (t < nparts) ? g_partial[t] : 0;
        part[t] = v; orig[t] = v;
    }
    __syncthreads();
    for (int off = 1; off < 128; off <<= 1) {
        int u = (t < 128 && t >= off) ? part[t - off] : 0;
        __syncthreads();
        if (t < 128) part[t] += u;
        __syncthreads();
    }
    int blk_off = part[blockIdx.x] - orig[blockIdx.x];  // exclusive prefix

    int i = blockIdx.x * 1024 + t;
    int d = (i < NN) ? g_indeg[i] : 0;
    s[t] = d;
    __syncthreads();
    for (int off = 1; off < 1024; off <<= 1) {
        int u = (t >= off) ? s[t - off] : 0;
        __syncthreads();
        s[t] += u;
        __syncthreads();
    }
    if (i < NN) {
        int rp = s[t] - d + blk_off;
        g_rowptr[i] = rp;
        g_cursor[i] = rp;
        g_innorm[i]  = rsqrtf((float)max(d, 1));
        g_outnorm[i] = rsqrtf((float)max(g_outdeg[i], 1));
    }
    if (i == 0) g_rowptr[NN] = EE;
}

__global__ void __launch_bounds__(256) fill_kernel(const int4* __restrict__ src4, const int4* __restrict__ dst4) {
    int i = blockIdx.x * blockDim.x + threadIdx.x;
    if (i < EE / 4) {
        int4 s = src4[i], d = dst4[i];
        g_csrc[atomicAdd(&g_cursor[d.x], 1)] = s.x;
        g_csrc[atomicAdd(&g_cursor[d.y], 1)] = s.y;
        g_csrc[atomicAdd(&g_cursor[d.z], 1)] = s.z;
        g_csrc[atomicAdd(&g_cursor[d.w], 1)] = s.w;
    }
}

// ---------------- aggregation: one warp per node, bf16 gather, fp32 accum, bf16 out ----------------
__device__ __forceinline__ float4 bf4_to_f4(uint2 p) {
    __nv_bfloat162 b0 = *reinterpret_cast<__nv_bfloat162*>(&p.x);
    __nv_bfloat162 b1 = *reinterpret_cast<__nv_bfloat162*>(&p.y);
    float2 f0 = __bfloat1622float2(b0);
    float2 f1 = __bfloat1622float2(b1);
    return make_float4(f0.x, f0.y, f1.x, f1.y);
}

template <bool SCALE>
__global__ void __launch_bounds__(256) agg_kernel() {
    int w = (blockIdx.x * blockDim.x + threadIdx.x) >> 5;
    if (w >= NN) return;
    int lane = threadIdx.x & 31;
    int s = g_rowptr[w], e = g_rowptr[w + 1];
    const uint2* __restrict__ X = (const uint2*)g_xb;
    float4 acc = make_float4(0.f, 0.f, 0.f, 0.f);
    int j = s;
    for (; j + 3 < e; j += 4) {
        int u0 = g_csrc[j], u1 = g_csrc[j + 1], u2 = g_csrc[j + 2], u3 = g_csrc[j + 3];
        float4 a = bf4_to_f4(X[u0 * 32 + lane]);
        float4 b = bf4_to_f4(X[u1 * 32 + lane]);
        float4 c = bf4_to_f4(X[u2 * 32 + lane]);
        float4 d = bf4_to_f4(X[u3 * 32 + lane]);
        if (SCALE) {
            float n0 = g_outnorm[u0], n1 = g_outnorm[u1], n2 = g_outnorm[u2], n3 = g_outnorm[u3];
            acc.x += a.x * n0 + b.x * n1 + c.x * n2 + d.x * n3;
            acc.y += a.y * n0 + b.y * n1 + c.y * n2 + d.y * n3;
            acc.z += a.z * n0 + b.z * n1 + c.z * n2 + d.z * n3;
            acc.w += a.w * n0 + b.w * n1 + c.w * n2 + d.w * n3;
        } else {
            acc.x += a.x + b.x + c.x + d.x;
            acc.y += a.y + b.y + c.y + d.y;
            acc.z += a.z + b.z + c.z + d.z;
            acc.w += a.w + b.w + c.w + d.w;
        }
    }
    for (; j < e; j++) {
        int u = g_csrc[j];
        float4 a = bf4_to_f4(X[u * 32 + lane]);
        float n = SCALE ? g_outnorm[u] : 1.f;
        acc.x += a.x * n; acc.y += a.y * n; acc.z += a.z * n; acc.w += a.w * n;
    }
    float inw = g_innorm[w];
    acc.x *= inw; acc.y *= inw; acc.z *= inw; acc.w *= inw;
    __nv_bfloat162 b0 = __floats2bfloat162_rn(acc.x, acc.y);
    __nv_bfloat162 b1 = __floats2bfloat162_rn(acc.z, acc.w);
    uint2 p;
    p.x = *reinterpret_cast<unsigned*>(&b0);
    p.y = *reinterpret_cast<unsigned*>(&b1);
    ((uint2*)g_aggb)[w * 32 + lane] = p;
}

// ---------------- mma.sync bf16 GEMM with ldmatrix fragment loads ----------------
#define SA 136  // smem row stride in bf16 elems (+16B pad -> conflict-free)

__device__ __forceinline__ unsigned smem_u32(const void* p) {
    unsigned a;
    asm("{ .reg .u64 t; cvta.to.shared.u64 t, %1; cvt.u32.u64 %0, t; }" : "=r"(a) : "l"(p));
    return a;
}
__device__ __forceinline__ void ldsm4(unsigned& r0, unsigned& r1, unsigned& r2, unsigned& r3, unsigned addr) {
    asm volatile("ldmatrix.sync.aligned.m8n8.x4.shared.b16 {%0,%1,%2,%3}, [%4];"
                 : "=r"(r0), "=r"(r1), "=r"(r2), "=r"(r3) : "r"(addr));
}
__device__ __forceinline__ void mma16816(float* c, const unsigned* a, const unsigned* b) {
    asm volatile(
        "mma.sync.aligned.m16n8k16.row.col.f32.bf16.bf16.f32 "
        "{%0,%1,%2,%3}, {%4,%5,%6,%7}, {%8,%9}, {%0,%1,%2,%3};"
        : "+f"(c[0]), "+f"(c[1]), "+f"(c[2]), "+f"(c[3])
        : "r"(a[0]), "r"(a[1]), "r"(a[2]), "r"(a[3]), "r"(b[0]), "r"(b[1]));
}

// full 128xNRx128 MMA stage from smem; fragments via ldmatrix
template <int NT>
__device__ __forceinline__ void mma_stage(const __nv_bfloat16* As, const __nv_bfloat16* Bs,
                                          int wm, int wn, int lane, float c[2][NT][4]) {
#pragma unroll
    for (int mt = 0; mt < 2; mt++)
#pragma unroll
        for (int nt = 0; nt < NT; nt++)
#pragma unroll
            for (int q = 0; q < 4; q++) c[mt][nt][q] = 0.f;

    // A: per mt, lanes point at rows wm*32+mt*16 + (lane&15), col (lane>>4)*8
    unsigned aAddr[2];
#pragma unroll
    for (int mt = 0; mt < 2; mt++) {
        int row = wm * 32 + mt * 16 + (lane & 15);
        int col = (lane >> 4) << 3;
        aAddr[mt] = smem_u32(As + row * SA + col);
    }
    // B: per pair p (nt=2p,2p+1): rows n0 + ((lane>>4)<<3) + (lane&7), col ((lane>>3)&1)*8
    unsigned bAddr[NT / 2];
#pragma unroll
    for (int p = 0; p < NT / 2; p++) {
        int n0 = wn * (NT * 8) + p * 16;
        int row = n0 + ((lane >> 4) << 3) + (lane & 7);
        int col = ((lane >> 3) & 1) << 3;
        bAddr[p] = smem_u32(Bs + row * SA + col);
    }

#pragma unroll
    for (int ks = 0; ks < 8; ks++) {
        unsigned koff = ks * 16 * 2;  // bytes
        unsigned af[2][4];
#pragma unroll
        for (int mt = 0; mt < 2; mt++)
            ldsm4(af[mt][0], af[mt][1], af[mt][2], af[mt][3], aAddr[mt] + koff);
        unsigned bfr[NT][2];
#pragma unroll
        for (int p = 0; p < NT / 2; p++)
            ldsm4(bfr[2 * p][0], bfr[2 * p][1], bfr[2 * p + 1][0], bfr[2 * p + 1][1], bAddr[p] + koff);
#pragma unroll
        for (int mt = 0; mt < 2; mt++)
#pragma unroll
            for (int nt = 0; nt < NT; nt++)
                mma16816(c[mt][nt], af[mt], bfr[nt]);
    }
}

// D[M,NR] = A[M,128] @ Bt[NR,128]^T; MODE 0: relu (*postscale if POST); 2: sigmoid.
template <int NR, int MODE, bool OUTB, bool POST>
__global__ void __launch_bounds__(256) mma_gemm_kernel(
    const __nv_bfloat16* __restrict__ A,
    const __nv_bfloat16* __restrict__ Bt,
    const float* __restrict__ bias,
    const float* __restrict__ postscale,
    void* __restrict__ outp, int M)
{
    constexpr int K = 128;
    constexpr int NT = NR / 16;
    extern __shared__ char smem[];
    __nv_bfloat16* As = (__nv_bfloat16*)smem;
    __nv_bfloat16* Bs = (__nv_bfloat16*)(smem + 128 * SA * 2);
    float* bs = (float*)(smem + 128 * SA * 2 + NR * SA * 2);

    int tid = threadIdx.x;
    int brow = blockIdx.x * 128;

    for (int i = tid; i < 128 * 16; i += 256) {
        int row = i >> 4, seg = i & 15;
        uint4 v = make_uint4(0u, 0u, 0u, 0u);
        int gr = brow + row;
        if (gr < M) v = *(const uint4*)(A + (size_t)gr * K + seg * 8);
        *(uint4*)(As + row * SA + seg * 8) = v;
    }
    for (int i = tid; i < NR * 16; i += 256) {
        int row = i >> 4, seg = i & 15;
        *(uint4*)(Bs + row * SA + seg * 8) = *(const uint4*)(Bt + (size_t)row * K + seg * 8);
    }
    if (tid < NR) bs[tid] = bias[tid];
    __syncthreads();

    int wid = tid >> 5, lane = tid & 31;
    int wm = wid & 3, wn = wid >> 2;
    int gid = lane >> 2, tig = lane & 3;

    float c[2][NT][4];
    mma_stage<NT>(As, Bs, wm, wn, lane, c);

#pragma unroll
    for (int mt = 0; mt < 2; mt++) {
        int r0 = brow + wm * 32 + mt * 16 + gid;
        int r1 = r0 + 8;
        float p0 = 1.f, p1 = 1.f;
        if (POST) {
            if (r0 < M) p0 = postscale[r0];
            if (r1 < M) p1 = postscale[r1];
        }
#pragma unroll
        for (int nt = 0; nt < NT; nt++) {
            int col = wn * (NT * 8) + nt * 8 + tig * 2;
            float b0v = bs[col], b1v = bs[col + 1];
            float v0 = c[mt][nt][0] + b0v, v1 = c[mt][nt][1] + b1v;
            float v2 = c[mt][nt][2] + b0v, v3 = c[mt][nt][3] + b1v;
            if (MODE == 2) {
                v0 = 1.f / (1.f + __expf(-v0)); v1 = 1.f / (1.f + __expf(-v1));
                v2 = 1.f / (1.f + __expf(-v2)); v3 = 1.f / (1.f + __expf(-v3));
            } else {
                v0 = fmaxf(v0, 0.f) * p0; v1 = fmaxf(v1, 0.f) * p0;
                v2 = fmaxf(v2, 0.f) * p1; v3 = fmaxf(v3, 0.f) * p1;
            }
            if (OUTB) {
                __nv_bfloat16* ob = (__nv_bfloat16*)outp;
                if (r0 < M) {
                    __nv_bfloat162 pk = __floats2bfloat162_rn(v0, v1);
                    *(unsigned*)(ob + (size_t)r0 * NR + col) = *reinterpret_cast<unsigned*>(&pk);
                }
                if (r1 < M) {
                    __nv_bfloat162 pk = __floats2bfloat162_rn(v2, v3);
                    *(unsigned*)(ob + (size_t)r1 * NR + col) = *reinterpret_cast<unsigned*>(&pk);
                }
            } else {
                float* of = (float*)outp;
                if (r0 < M) *(float2*)(of + (size_t)r0 * NR + col) = make_float2(v0, v1);
                if (r1 < M) *(float2*)(of + (size_t)r1 * NR + col) = make_float2(v2, v3);
            }
        }
    }
}

// ---------------- launch ----------------
extern "C" void kernel_launch(void* const* d_in, const int* in_sizes, int n_in,
                              void* d_out, int out_size) {
    const float* x   = (const float*)d_in[0];
    const int*   src = (const int*)d_in[1];
    const int*   dst = (const int*)d_in[2];
    const float* W1  = (const float*)d_in[3];
    const float* b1  = (const float*)d_in[4];
    const float* W2  = (const float*)d_in[5];
    const float* b2  = (const float*)d_in[6];
    const float* Wm1 = (const float*)d_in[7];
    const float* bm1 = (const float*)d_in[8];
    const float* Wm2 = (const float*)d_in[9];
    const float* bm2 = (const float*)d_in[10];
    float* out = (float*)d_out;

    void *p_xb, *p_aggb, *p_hb, *p_mb, *p_w1t, *p_w2t, *p_wm1t, *p_wm2t, *p_outnorm;
    cudaGetSymbolAddress(&p_xb, g_xb);
    cudaGetSymbolAddress(&p_aggb, g_aggb);
    cudaGetSymbolAddress(&p_hb, g_hb);
    cudaGetSymbolAddress(&p_mb, g_mb);
    cudaGetSymbolAddress(&p_w1t, g_w1t);
    cudaGetSymbolAddress(&p_w2t, g_w2t);
    cudaGetSymbolAddress(&p_wm1t, g_wm1t);
    cudaGetSymbolAddress(&p_wm2t, g_wm2t);
    cudaGetSymbolAddress(&p_outnorm, g_outnorm);

    constexpr int SMEM_G128 = 128 * SA * 2 + 128 * SA * 2 + 512;  // 70144
    constexpr int SMEM_G64  = 128 * SA * 2 + 64 * SA * 2 + 256;   // 52480
    cudaFuncSetAttribute(mma_gemm_kernel<128, 0, true, true>,
                         cudaFuncAttributeMaxDynamicSharedMemorySize, SMEM_G128);
    cudaFuncSetAttribute(mma_gemm_kernel<128, 0, true, false>,
                         cudaFuncAttributeMaxDynamicSharedMemorySize, SMEM_G128);
    cudaFuncSetAttribute(mma_gemm_kernel<64, 2, false, false>,
                         cudaFuncAttributeMaxDynamicSharedMemorySize, SMEM_G64);

    const int TB = 256;
    int e4blk = (EE / 4 + TB - 1) / TB;
    int sblk = (NN + 1023) / 1024;  // 98
    int gblk = (NN + 127) / 128;    // 782
    int ablk = (NN * 32 + TB - 1) / TB;

    // prep (zero + weights + x->bf16) in one launch, then graph preprocessing
    prep_kernel<<<ablk, TB>>>((const float4*)x, W1, W2, Wm1, Wm2);
    degree_kernel<<<e4blk, TB>>>((const int4*)src, (const int4*)dst);
    scan_reduce_kernel<<<sblk, 256>>>();
    scan_down_kernel<<<sblk, 1024>>>(sblk);
    fill_kernel<<<e4blk, TB>>>((const int4*)src, (const int4*)dst);

    // conv1
    agg_kernel<true><<<ablk, TB>>>();
    mma_gemm_kernel<128, 0, true, true><<<gblk, 256, SMEM_G128>>>(
        (const __nv_bfloat16*)p_aggb, (const __nv_bfloat16*)p_w1t, b1,
        (const float*)p_outnorm, p_xb, NN);

    // conv2
    agg_kernel<false><<<ablk, TB>>>();
    mma_gemm_kernel<128, 0, true, false><<<gblk, 256, SMEM_G128>>>(
        (const __nv_bfloat16*)p_aggb, (const __nv_bfloat16*)p_w2t, b2,
        nullptr, p_hb, NN);

    // MLP head
    mma_gemm_kernel<128, 0, true, false><<<gblk, 256, SMEM_G128>>>(
        (const __nv_bfloat16*)p_hb, (const __nv_bfloat16*)p_wm1t, bm1,
        nullptr, p_mb, NN);
    mma_gemm_kernel<64, 2, false, false><<<gblk, 256, SMEM_G64>>>(
        (const __nv_bfloat16*)p_mb, (const __nv_bfloat16*)p_wm2t, bm2,
        nullptr, out, NN);
}

// round 13
// speedup vs baseline: 1.0450x; 1.0450x over previous
#include <cuda_runtime.h>
#include <cuda_bf16.h>
#include <cstdint>
#include <math.h>

#define NN 100000
#define EE 3200000
#define FF 128

// ---------------- static device scratch (no allocations allowed) ----------------
__device__ __nv_bfloat16 g_xb[NN * FF];   // bf16 gather source (x, then h1*outnorm)
__device__ __nv_bfloat16 g_aggb[NN * FF]; // bf16 aggregation output
__device__ __nv_bfloat16 g_hb[NN * FF];   // conv2 output
__device__ __nv_bfloat16 g_mb[NN * FF];   // mlp hidden
__device__ __nv_bfloat16 g_w1t[FF * FF];  // W1^T bf16 [n][k]
__device__ __nv_bfloat16 g_w2t[FF * FF];
__device__ __nv_bfloat16 g_wm1t[FF * FF];
__device__ __nv_bfloat16 g_wm2t[64 * FF];
__device__ float g_outnorm[NN];
__device__ float g_innorm[NN];
__device__ int   g_outdeg[NN];
__device__ int   g_indeg[NN];
__device__ int   g_rowptr[NN + 1];
__device__ int   g_cursor[NN];
__device__ int   g_partial[128];
__device__ int   g_csrc[EE];              // CSR (by dst) column indices = src nodes

// ---------------- prep: zero counters + weight transpose/bf16 + x->bf16 (launch-merge of R10's 3 kernels) ----------------
__global__ void __launch_bounds__(256) prep_kernel(
    const float4* __restrict__ x,
    const float* __restrict__ W1, const float* __restrict__ W2,
    const float* __restrict__ Wm1, const float* __restrict__ Wm2) {
    int i = blockIdx.x * blockDim.x + threadIdx.x;
    if (i < NN) { g_outdeg[i] = 0; g_indeg[i] = 0; }
    if (i < 16384) {
        int k = i >> 7, n = i & 127;
        g_w1t[n * 128 + k] = __float2bfloat16(W1[i]);
        g_w2t[n * 128 + k] = __float2bfloat16(W2[i]);
        g_wm1t[n * 128 + k] = __float2bfloat16(Wm1[i]);
        if (i < 8192) {
            int k2 = i >> 6, n2 = i & 63;
            g_wm2t[n2 * 128 + k2] = __float2bfloat16(Wm2[i]);
        }
    }
    if (i < NN * 32) {
        float4 v = x[i];
        __nv_bfloat162 b0 = __floats2bfloat162_rn(v.x, v.y);
        __nv_bfloat162 b1 = __floats2bfloat162_rn(v.z, v.w);
        uint2 p;
        p.x = *reinterpret_cast<unsigned*>(&b0);
        p.y = *reinterpret_cast<unsigned*>(&b1);
        ((uint2*)g_xb)[i] = p;
    }
}

// ---------------- graph preprocessing (scalar, as in R10) ----------------
__global__ void __launch_bounds__(256) degree_kernel(const int* __restrict__ src, const int* __restrict__ dst) {
    int e = blockIdx.x * blockDim.x + threadIdx.x;
    if (e < EE) {
        atomicAdd(&g_outdeg[src[e]], 1);
        atomicAdd(&g_indeg[dst[e]], 1);
    }
}

__global__ void __launch_bounds__(256) scan_reduce_kernel() {
    __shared__ int s[256];
    int t = threadIdx.x;
    int base = blockIdx.x * 1024;
    int v = 0;
#pragma unroll
    for (int j = 0; j < 4; j++) {
        int i = base + t + j * 256;
        if (i < NN) v += g_indeg[i];
    }
    s[t] = v;
    __syncthreads();
    for (int off = 128; off > 0; off >>= 1) {
        if (t < off) s[t] += s[t + off];
        __syncthreads();
    }
    if (t == 0) g_partial[blockIdx.x] = s[0];
}

// downsweep: inline exclusive scan of partials + block-local scan -> rowptr, cursor, norms
__global__ void __launch_bounds__(1024) scan_down_kernel(int nparts) {
    __shared__ int part[128];
    __shared__ int orig[128];
    __shared__ int s[1024];
    int t = threadIdx.x;
    if (t < 128) {
        int v = (t < nparts) ? g_partial[t] : 0;
        part[t] = v; orig[t] = v;
    }
    __syncthreads();
    for (int off = 1; off < 128; off <<= 1) {
        int u = (t < 128 && t >= off) ? part[t - off] : 0;
        __syncthreads();
        if (t < 128) part[t] += u;
        __syncthreads();
    }
    int blk_off = part[blockIdx.x] - orig[blockIdx.x];  // exclusive prefix

    int i = blockIdx.x * 1024 + t;
    int d = (i < NN) ? g_indeg[i] : 0;
    s[t] = d;
    __syncthreads();
    for (int off = 1; off < 1024; off <<= 1) {
        int u = (t >= off) ? s[t - off] : 0;
        __syncthreads();
        s[t] += u;
        __syncthreads();
    }
    if (i < NN) {
        int rp = s[t] - d + blk_off;
        g_rowptr[i] = rp;
        g_cursor[i] = rp;
        g_innorm[i]  = rsqrtf((float)max(d, 1));
        g_outnorm[i] = rsqrtf((float)max(g_outdeg[i], 1));
    }
    if (i == 0) g_rowptr[NN] = EE;
}

__global__ void __launch_bounds__(256) fill_kernel(const int* __restrict__ src, const int* __restrict__ dst) {
    int e = blockIdx.x * blockDim.x + threadIdx.x;
    if (e < EE) {
        int pos = atomicAdd(&g_cursor[dst[e]], 1);
        g_csrc[pos] = src[e];
    }
}

// ---------------- aggregation: one warp per node, bf16 gather, fp32 accum, bf16 out ----------------
__device__ __forceinline__ float4 bf4_to_f4(uint2 p) {
    __nv_bfloat162 b0 = *reinterpret_cast<__nv_bfloat162*>(&p.x);
    __nv_bfloat162 b1 = *reinterpret_cast<__nv_bfloat162*>(&p.y);
    float2 f0 = __bfloat1622float2(b0);
    float2 f1 = __bfloat1622float2(b1);
    return make_float4(f0.x, f0.y, f1.x, f1.y);
}

template <bool SCALE>
__global__ void __launch_bounds__(256) agg_kernel() {
    int w = (blockIdx.x * blockDim.x + threadIdx.x) >> 5;
    if (w >= NN) return;
    int lane = threadIdx.x & 31;
    int s = g_rowptr[w], e = g_rowptr[w + 1];
    const uint2* __restrict__ X = (const uint2*)g_xb;
    float4 acc = make_float4(0.f, 0.f, 0.f, 0.f);
    int j = s;
    for (; j + 3 < e; j += 4) {
        int u0 = g_csrc[j], u1 = g_csrc[j + 1], u2 = g_csrc[j + 2], u3 = g_csrc[j + 3];
        float4 a = bf4_to_f4(X[u0 * 32 + lane]);
        float4 b = bf4_to_f4(X[u1 * 32 + lane]);
        float4 c = bf4_to_f4(X[u2 * 32 + lane]);
        float4 d = bf4_to_f4(X[u3 * 32 + lane]);
        if (SCALE) {
            float n0 = g_outnorm[u0], n1 = g_outnorm[u1], n2 = g_outnorm[u2], n3 = g_outnorm[u3];
            acc.x += a.x * n0 + b.x * n1 + c.x * n2 + d.x * n3;
            acc.y += a.y * n0 + b.y * n1 + c.y * n2 + d.y * n3;
            acc.z += a.z * n0 + b.z * n1 + c.z * n2 + d.z * n3;
            acc.w += a.w * n0 + b.w * n1 + c.w * n2 + d.w * n3;
        } else {
            acc.x += a.x + b.x + c.x + d.x;
            acc.y += a.y + b.y + c.y + d.y;
            acc.z += a.z + b.z + c.z + d.z;
            acc.w += a.w + b.w + c.w + d.w;
        }
    }
    for (; j < e; j++) {
        int u = g_csrc[j];
        float4 a = bf4_to_f4(X[u * 32 + lane]);
        float n = SCALE ? g_outnorm[u] : 1.f;
        acc.x += a.x * n; acc.y += a.y * n; acc.z += a.z * n; acc.w += a.w * n;
    }
    float inw = g_innorm[w];
    acc.x *= inw; acc.y *= inw; acc.z *= inw; acc.w *= inw;
    __nv_bfloat162 b0 = __floats2bfloat162_rn(acc.x, acc.y);
    __nv_bfloat162 b1 = __floats2bfloat162_rn(acc.z, acc.w);
    uint2 p;
    p.x = *reinterpret_cast<unsigned*>(&b0);
    p.y = *reinterpret_cast<unsigned*>(&b1);
    ((uint2*)g_aggb)[w * 32 + lane] = p;
}

// ---------------- mma.sync bf16 GEMM (R10: direct LDS fragment loads) ----------------
template <int NR, int MODE, bool OUTB, bool POST>
__global__ void __launch_bounds__(256) mma_gemm_kernel(
    const __nv_bfloat16* __restrict__ A,
    const __nv_bfloat16* __restrict__ Bt,
    const float* __restrict__ bias,
    const float* __restrict__ postscale,
    void* __restrict__ outp, int M)
{
    constexpr int K = 128;
    constexpr int SA = 136;                // row stride in bf16 elems (+16B pad -> conflict-free frags)
    constexpr int NT = NR / 16;            // n-tiles (8 wide) per warp: 8 (NR=128) or 4 (NR=64)
    extern __shared__ char smem[];
    __nv_bfloat16* As = (__nv_bfloat16*)smem;                       // 128 x SA
    __nv_bfloat16* Bs = (__nv_bfloat16*)(smem + 128 * SA * 2);      // NR x SA
    float* bs = (float*)(smem + 128 * SA * 2 + NR * SA * 2);

    int tid = threadIdx.x;
    int brow = blockIdx.x * 128;

    // load A tile (uint4 per 8 elems)
    for (int i = tid; i < 128 * 16; i += 256) {
        int row = i >> 4, seg = i & 15;
        uint4 v = make_uint4(0u, 0u, 0u, 0u);
        int gr = brow + row;
        if (gr < M) v = *(const uint4*)(A + (size_t)gr * K + seg * 8);
        *(uint4*)(As + row * SA + seg * 8) = v;
    }
    // load B tile
    for (int i = tid; i < NR * 16; i += 256) {
        int row = i >> 4, seg = i & 15;
        *(uint4*)(Bs + row * SA + seg * 8) = *(const uint4*)(Bt + (size_t)row * K + seg * 8);
    }
    if (tid < NR) bs[tid] = bias[tid];
    __syncthreads();

    int wid = tid >> 5, lane = tid & 31;
    int wm = wid & 3, wn = wid >> 2;       // wm: 0..3 (32 rows each), wn: 0..1 (NR/2 cols each)
    int gid = lane >> 2, tig = lane & 3;

    float c[2][NT][4];
#pragma unroll
    for (int mt = 0; mt < 2; mt++)
#pragma unroll
        for (int nt = 0; nt < NT; nt++)
#pragma unroll
            for (int q = 0; q < 4; q++) c[mt][nt][q] = 0.f;

#pragma unroll
    for (int ks = 0; ks < 8; ks++) {
        int k0 = ks * 16;
        unsigned af[2][4];
#pragma unroll
        for (int mt = 0; mt < 2; mt++) {
            const __nv_bfloat16* p = As + (wm * 32 + mt * 16 + gid) * SA + k0 + tig * 2;
            af[mt][0] = *(const unsigned*)(p);
            af[mt][1] = *(const unsigned*)(p + 8 * SA);
            af[mt][2] = *(const unsigned*)(p + 8);
            af[mt][3] = *(const unsigned*)(p + 8 * SA + 8);
        }
        unsigned bf[NT][2];
#pragma unroll
        for (int nt = 0; nt < NT; nt++) {
            const __nv_bfloat16* q = Bs + (wn * (NT * 8) + nt * 8 + gid) * SA + k0 + tig * 2;
            bf[nt][0] = *(const unsigned*)(q);
            bf[nt][1] = *(const unsigned*)(q + 8);
        }
#pragma unroll
        for (int mt = 0; mt < 2; mt++)
#pragma unroll
            for (int nt = 0; nt < NT; nt++) {
                asm volatile(
                    "mma.sync.aligned.m16n8k16.row.col.f32.bf16.bf16.f32 "
                    "{%0,%1,%2,%3}, {%4,%5,%6,%7}, {%8,%9}, {%0,%1,%2,%3};"
                    : "+f"(c[mt][nt][0]), "+f"(c[mt][nt][1]),
                      "+f"(c[mt][nt][2]), "+f"(c[mt][nt][3])
                    : "r"(af[mt][0]), "r"(af[mt][1]), "r"(af[mt][2]), "r"(af[mt][3]),
                      "r"(bf[nt][0]), "r"(bf[nt][1]));
            }
    }

    // epilogue: c0,c1 -> (r, col..col+1); c2,c3 -> (r+8, col..col+1)
#pragma unroll
    for (int mt = 0; mt < 2; mt++) {
        int r0 = brow + wm * 32 + mt * 16 + gid;
        int r1 = r0 + 8;
        float p0 = 1.f, p1 = 1.f;
        if (POST) {
            if (r0 < M) p0 = postscale[r0];
            if (r1 < M) p1 = postscale[r1];
        }
#pragma unroll
        for (int nt = 0; nt < NT; nt++) {
            int col = wn * (NT * 8) + nt * 8 + tig * 2;
            float b0v = bs[col], b1v = bs[col + 1];
            float v0 = c[mt][nt][0] + b0v, v1 = c[mt][nt][1] + b1v;
            float v2 = c[mt][nt][2] + b0v, v3 = c[mt][nt][3] + b1v;
            if (MODE == 2) {
                v0 = 1.f / (1.f + __expf(-v0)); v1 = 1.f / (1.f + __expf(-v1));
                v2 = 1.f / (1.f + __expf(-v2)); v3 = 1.f / (1.f + __expf(-v3));
            } else {
                v0 = fmaxf(v0, 0.f) * p0; v1 = fmaxf(v1, 0.f) * p0;
                v2 = fmaxf(v2, 0.f) * p1; v3 = fmaxf(v3, 0.f) * p1;
            }
            if (OUTB) {
                __nv_bfloat16* ob = (__nv_bfloat16*)outp;
                if (r0 < M) {
                    __nv_bfloat162 pk = __floats2bfloat162_rn(v0, v1);
                    *(unsigned*)(ob + (size_t)r0 * NR + col) = *reinterpret_cast<unsigned*>(&pk);
                }
                if (r1 < M) {
                    __nv_bfloat162 pk = __floats2bfloat162_rn(v2, v3);
                    *(unsigned*)(ob + (size_t)r1 * NR + col) = *reinterpret_cast<unsigned*>(&pk);
                }
            } else {
                float* of = (float*)outp;
                if (r0 < M) *(float2*)(of + (size_t)r0 * NR + col) = make_float2(v0, v1);
                if (r1 < M) *(float2*)(of + (size_t)r1 * NR + col) = make_float2(v2, v3);
            }
        }
    }
}

// ---------------- launch ----------------
extern "C" void kernel_launch(void* const* d_in, const int* in_sizes, int n_in,
                              void* d_out, int out_size) {
    const float* x   = (const float*)d_in[0];
    const int*   src = (const int*)d_in[1];
    const int*   dst = (const int*)d_in[2];
    const float* W1  = (const float*)d_in[3];
    const float* b1  = (const float*)d_in[4];
    const float* W2  = (const float*)d_in[5];
    const float* b2  = (const float*)d_in[6];
    const float* Wm1 = (const float*)d_in[7];
    const float* bm1 = (const float*)d_in[8];
    const float* Wm2 = (const float*)d_in[9];
    const float* bm2 = (const float*)d_in[10];
    float* out = (float*)d_out;

    void *p_xb, *p_aggb, *p_hb, *p_mb, *p_w1t, *p_w2t, *p_wm1t, *p_wm2t, *p_outnorm;
    cudaGetSymbolAddress(&p_xb, g_xb);
    cudaGetSymbolAddress(&p_aggb, g_aggb);
    cudaGetSymbolAddress(&p_hb, g_hb);
    cudaGetSymbolAddress(&p_mb, g_mb);
    cudaGetSymbolAddress(&p_w1t, g_w1t);
    cudaGetSymbolAddress(&p_w2t, g_w2t);
    cudaGetSymbolAddress(&p_wm1t, g_wm1t);
    cudaGetSymbolAddress(&p_wm2t, g_wm2t);
    cudaGetSymbolAddress(&p_outnorm, g_outnorm);

    // smem: A 128*136*2 + B NR*136*2 + bias NR*4
    constexpr int SMEM_G128 = 128 * 136 * 2 + 128 * 136 * 2 + 512;  // 70144
    constexpr int SMEM_G64  = 128 * 136 * 2 + 64 * 136 * 2 + 256;   // 52480
    cudaFuncSetAttribute(mma_gemm_kernel<128, 0, true, true>,
                         cudaFuncAttributeMaxDynamicSharedMemorySize, SMEM_G128);
    cudaFuncSetAttribute(mma_gemm_kernel<128, 0, true, false>,
                         cudaFuncAttributeMaxDynamicSharedMemorySize, SMEM_G128);
    cudaFuncSetAttribute(mma_gemm_kernel<64, 2, false, false>,
                         cudaFuncAttributeMaxDynamicSharedMemorySize, SMEM_G64);

    const int TB = 256;
    int eblk = (EE + TB - 1) / TB;
    int sblk = (NN + 1023) / 1024;  // 98
    int gblk = (NN + 127) / 128;    // 782
    int ablk = (NN * 32 + TB - 1) / TB;

    // prep (zero + weights + x->bf16) in one launch, then graph preprocessing
    prep_kernel<<<ablk, TB>>>((const float4*)x, W1, W2, Wm1, Wm2);
    degree_kernel<<<eblk, TB>>>(src, dst);
    scan_reduce_kernel<<<sblk, 256>>>();
    scan_down_kernel<<<sblk, 1024>>>(sblk);
    fill_kernel<<<eblk, TB>>>(src, dst);

    // conv1
    agg_kernel<true><<<ablk, TB>>>();
    mma_gemm_kernel<128, 0, true, true><<<gblk, 256, SMEM_G128>>>(
        (const __nv_bfloat16*)p_aggb, (const __nv_bfloat16*)p_w1t, b1,
        (const float*)p_outnorm, p_xb, NN);

    // conv2
    agg_kernel<false><<<ablk, TB>>>();
    mma_gemm_kernel<128, 0, true, false><<<gblk, 256, SMEM_G128>>>(
        (const __nv_bfloat16*)p_aggb, (const __nv_bfloat16*)p_w2t, b2,
        nullptr, p_hb, NN);

    // MLP head
    mma_gemm_kernel<128, 0, true, false><<<gblk, 256, SMEM_G128>>>(
        (const __nv_bfloat16*)p_hb, (const __nv_bfloat16*)p_wm1t, bm1,
        nullptr, p_mb, NN);
    mma_gemm_kernel<64, 2, false, false><<<gblk, 256, SMEM_G64>>>(
        (const __nv_bfloat16*)p_mb, (const __nv_bfloat16*)p_wm2t, bm2,
        nullptr, out, NN);
}

// round 14
// speedup vs baseline: 1.1056x; 1.0580x over previous
#include <cuda_runtime.h>
#include <cuda_bf16.h>
#include <cstdint>
#include <math.h>

#define NN 100000
#define EE 3200000
#define FF 128

// ---------------- static device scratch (no allocations allowed) ----------------
__device__ __nv_bfloat16 g_xb[NN * FF];   // bf16 gather source (x, then h1*outnorm)
__device__ __nv_bfloat16 g_aggb[NN * FF]; // bf16 aggregation output
__device__ __nv_bfloat16 g_hb[NN * FF];   // conv2 output
__device__ __nv_bfloat16 g_mb[NN * FF];   // mlp hidden
__device__ __nv_bfloat16 g_w1t[FF * FF];  // W1^T bf16 [n][k]
__device__ __nv_bfloat16 g_w2t[FF * FF];
__device__ __nv_bfloat16 g_wm1t[FF * FF];
__device__ __nv_bfloat16 g_wm2t[64 * FF];
__device__ float g_outnorm[NN];
__device__ float g_innorm[NN];
__device__ int   g_outdeg[NN];
__device__ int   g_indeg[NN];
__device__ int   g_rowptr[NN + 1];
__device__ int   g_cursor[NN];
__device__ int   g_partial[128];
__device__ int   g_csrc[EE];              // CSR (by dst) column indices = src nodes

// ---------------- packed f32x2 helpers ----------------
__device__ __forceinline__ unsigned prmt0(unsigned a, unsigned sel) {
    unsigned r;
    asm("prmt.b32 %0, %1, 0, %2;" : "=r"(r) : "r"(a), "r"(sel));
    return r;
}
__device__ __forceinline__ unsigned long long pack64(unsigned lo, unsigned hi) {
    unsigned long long r;
    asm("mov.b64 %0, {%1, %2};" : "=l"(r) : "r"(lo), "r"(hi));
    return r;
}
__device__ __forceinline__ unsigned long long pack2_dup(float x) {
    unsigned long long r;
    asm("mov.b64 %0, {%1, %1};" : "=l"(r) : "r"(__float_as_uint(x)));
    return r;
}
__device__ __forceinline__ void add2(unsigned long long& d, unsigned long long a) {
    asm("add.rn.f32x2 %0, %0, %1;" : "+l"(d) : "l"(a));
}
__device__ __forceinline__ void fma2(unsigned long long& d, unsigned long long a, unsigned long long b) {
    asm("fma.rn.f32x2 %0, %1, %2, %0;" : "+l"(d) : "l"(a), "l"(b));
}
__device__ __forceinline__ float2 unpack2(unsigned long long v) {
    unsigned lo, hi;
    asm("mov.b64 {%0, %1}, %2;" : "=r"(lo), "=r"(hi) : "l"(v));
    float2 r; r.x = __uint_as_float(lo); r.y = __uint_as_float(hi);
    return r;
}

// ---------------- prep: zero counters + weight transpose/bf16 + x->bf16 ----------------
__global__ void __launch_bounds__(256) prep_kernel(
    const float4* __restrict__ x,
    const float* __restrict__ W1, const float* __restrict__ W2,
    const float* __restrict__ Wm1, const float* __restrict__ Wm2) {
    int i = blockIdx.x * blockDim.x + threadIdx.x;
    if (i < NN) { g_outdeg[i] = 0; g_indeg[i] = 0; }
    if (i < 16384) {
        int k = i >> 7, n = i & 127;
        g_w1t[n * 128 + k] = __float2bfloat16(W1[i]);
        g_w2t[n * 128 + k] = __float2bfloat16(W2[i]);
        g_wm1t[n * 128 + k] = __float2bfloat16(Wm1[i]);
        if (i < 8192) {
            int k2 = i >> 6, n2 = i & 63;
            g_wm2t[n2 * 128 + k2] = __float2bfloat16(Wm2[i]);
        }
    }
    if (i < NN * 32) {
        float4 v = x[i];
        __nv_bfloat162 b0 = __floats2bfloat162_rn(v.x, v.y);
        __nv_bfloat162 b1 = __floats2bfloat162_rn(v.z, v.w);
        uint2 p;
        p.x = *reinterpret_cast<unsigned*>(&b0);
        p.y = *reinterpret_cast<unsigned*>(&b1);
        ((uint2*)g_xb)[i] = p;
    }
}

// ---------------- graph preprocessing ----------------
__global__ void __launch_bounds__(256) degree_kernel(const int* __restrict__ src, const int* __restrict__ dst) {
    int e = blockIdx.x * blockDim.x + threadIdx.x;
    if (e < EE) {
        atomicAdd(&g_outdeg[src[e]], 1);
        atomicAdd(&g_indeg[dst[e]], 1);
    }
}

__global__ void __launch_bounds__(256) scan_reduce_kernel() {
    __shared__ int s[256];
    int t = threadIdx.x;
    int base = blockIdx.x * 1024;
    int v = 0;
#pragma unroll
    for (int j = 0; j < 4; j++) {
        int i = base + t + j * 256;
        if (i < NN) v += g_indeg[i];
    }
    s[t] = v;
    __syncthreads();
    for (int off = 128; off > 0; off >>= 1) {
        if (t < off) s[t] += s[t + off];
        __syncthreads();
    }
    if (t == 0) g_partial[blockIdx.x] = s[0];
}

__global__ void __launch_bounds__(1024) scan_down_kernel(int nparts) {
    __shared__ int part[128];
    __shared__ int orig[128];
    __shared__ int s[1024];
    int t = threadIdx.x;
    if (t < 128) {
        int v = (t < nparts) ? g_partial[t] : 0;
        part[t] = v; orig[t] = v;
    }
    __syncthreads();
    for (int off = 1; off < 128; off <<= 1) {
        int u = (t < 128 && t >= off) ? part[t - off] : 0;
        __syncthreads();
        if (t < 128) part[t] += u;
        __syncthreads();
    }
    int blk_off = part[blockIdx.x] - orig[blockIdx.x];  // exclusive prefix

    int i = blockIdx.x * 1024 + t;
    int d = (i < NN) ? g_indeg[i] : 0;
    s[t] = d;
    __syncthreads();
    for (int off = 1; off < 1024; off <<= 1) {
        int u = (t >= off) ? s[t - off] : 0;
        __syncthreads();
        s[t] += u;
        __syncthreads();
    }
    if (i < NN) {
        int rp = s[t] - d + blk_off;
        g_rowptr[i] = rp;
        g_cursor[i] = rp;
        g_innorm[i]  = rsqrtf((float)max(d, 1));
        g_outnorm[i] = rsqrtf((float)max(g_outdeg[i], 1));
    }
    if (i == 0) g_rowptr[NN] = EE;
}

__global__ void __launch_bounds__(256) fill_kernel(const int* __restrict__ src, const int* __restrict__ dst) {
    int e = blockIdx.x * blockDim.x + threadIdx.x;
    if (e < EE) {
        int pos = atomicAdd(&g_cursor[dst[e]], 1);
        g_csrc[pos] = src[e];
    }
}

// ---------------- aggregation: warp/node, 8-edge unroll, PRMT + packed f32x2 accum ----------------
// bf16 feats f0..f3 in uint2; f32(bf16) = bf16<<16 -> PRMT zero-extend (bit-exact)
#define SEL_LO 0x1044u  // bytes [0,0,b0,b1] then [0,0,b2,b3] of .x -> f32x2 {f0,f1}
#define SEL_HI 0x3244u

template <bool SCALE>
__global__ void __launch_bounds__(256) agg_kernel() {
    int w = (blockIdx.x * blockDim.x + threadIdx.x) >> 5;
    if (w >= NN) return;
    int lane = threadIdx.x & 31;
    int s = g_rowptr[w], e = g_rowptr[w + 1];
    const uint2* __restrict__ X = (const uint2*)g_xb;
    unsigned long long a01 = 0ull, a23 = 0ull;  // packed f32x2 accumulators ({0,0} bits)
    int j = s;
    for (; j + 7 < e; j += 8) {
        int us[8];
#pragma unroll
        for (int q = 0; q < 8; q++) us[q] = g_csrc[j + q];
        uint2 vs[8];
#pragma unroll
        for (int q = 0; q < 8; q++) vs[q] = X[us[q] * 32 + lane];
        float ns[8];
        if (SCALE) {
#pragma unroll
            for (int q = 0; q < 8; q++) ns[q] = g_outnorm[us[q]];
        }
#pragma unroll
        for (int q = 0; q < 8; q++) {
            unsigned long long p01 = pack64(prmt0(vs[q].x, SEL_LO), prmt0(vs[q].x, SEL_HI));
            unsigned long long p23 = pack64(prmt0(vs[q].y, SEL_LO), prmt0(vs[q].y, SEL_HI));
            if (SCALE) {
                unsigned long long nn = pack2_dup(ns[q]);
                fma2(a01, p01, nn);
                fma2(a23, p23, nn);
            } else {
                add2(a01, p01);
                add2(a23, p23);
            }
        }
    }
    for (; j < e; j++) {
        int u = g_csrc[j];
        uint2 v = X[u * 32 + lane];
        unsigned long long p01 = pack64(prmt0(v.x, SEL_LO), prmt0(v.x, SEL_HI));
        unsigned long long p23 = pack64(prmt0(v.y, SEL_LO), prmt0(v.y, SEL_HI));
        if (SCALE) {
            unsigned long long nn = pack2_dup(g_outnorm[u]);
            fma2(a01, p01, nn);
            fma2(a23, p23, nn);
        } else {
            add2(a01, p01);
            add2(a23, p23);
        }
    }
    float inw = g_innorm[w];
    float2 f01 = unpack2(a01);
    float2 f23 = unpack2(a23);
    __nv_bfloat162 b0 = __floats2bfloat162_rn(f01.x * inw, f01.y * inw);
    __nv_bfloat162 b1 = __floats2bfloat162_rn(f23.x * inw, f23.y * inw);
    uint2 p;
    p.x = *reinterpret_cast<unsigned*>(&b0);
    p.y = *reinterpret_cast<unsigned*>(&b1);
    ((uint2*)g_aggb)[w * 32 + lane] = p;
}

// ---------------- mma.sync bf16 GEMM (R10: direct LDS fragment loads) ----------------
template <int NR, int MODE, bool OUTB, bool POST>
__global__ void __launch_bounds__(256) mma_gemm_kernel(
    const __nv_bfloat16* __restrict__ A,
    const __nv_bfloat16* __restrict__ Bt,
    const float* __restrict__ bias,
    const float* __restrict__ postscale,
    void* __restrict__ outp, int M)
{
    constexpr int K = 128;
    constexpr int SA = 136;                // row stride in bf16 elems (+16B pad -> conflict-free frags)
    constexpr int NT = NR / 16;            // n-tiles (8 wide) per warp: 8 (NR=128) or 4 (NR=64)
    extern __shared__ char smem[];
    __nv_bfloat16* As = (__nv_bfloat16*)smem;                       // 128 x SA
    __nv_bfloat16* Bs = (__nv_bfloat16*)(smem + 128 * SA * 2);      // NR x SA
    float* bs = (float*)(smem + 128 * SA * 2 + NR * SA * 2);

    int tid = threadIdx.x;
    int brow = blockIdx.x * 128;

    // load A tile (uint4 per 8 elems)
    for (int i = tid; i < 128 * 16; i += 256) {
        int row = i >> 4, seg = i & 15;
        uint4 v = make_uint4(0u, 0u, 0u, 0u);
        int gr = brow + row;
        if (gr < M) v = *(const uint4*)(A + (size_t)gr * K + seg * 8);
        *(uint4*)(As + row * SA + seg * 8) = v;
    }
    // load B tile
    for (int i = tid; i < NR * 16; i += 256) {
        int row = i >> 4, seg = i & 15;
        *(uint4*)(Bs + row * SA + seg * 8) = *(const uint4*)(Bt + (size_t)row * K + seg * 8);
    }
    if (tid < NR) bs[tid] = bias[tid];
    __syncthreads();

    int wid = tid >> 5, lane = tid & 31;
    int wm = wid & 3, wn = wid >> 2;       // wm: 0..3 (32 rows each), wn: 0..1 (NR/2 cols each)
    int gid = lane >> 2, tig = lane & 3;

    float c[2][NT][4];
#pragma unroll
    for (int mt = 0; mt < 2; mt++)
#pragma unroll
        for (int nt = 0; nt < NT; nt++)
#pragma unroll
            for (int q = 0; q < 4; q++) c[mt][nt][q] = 0.f;

#pragma unroll
    for (int ks = 0; ks < 8; ks++) {
        int k0 = ks * 16;
        unsigned af[2][4];
#pragma unroll
        for (int mt = 0; mt < 2; mt++) {
            const __nv_bfloat16* p = As + (wm * 32 + mt * 16 + gid) * SA + k0 + tig * 2;
            af[mt][0] = *(const unsigned*)(p);
            af[mt][1] = *(const unsigned*)(p + 8 * SA);
            af[mt][2] = *(const unsigned*)(p + 8);
            af[mt][3] = *(const unsigned*)(p + 8 * SA + 8);
        }
        unsigned bf[NT][2];
#pragma unroll
        for (int nt = 0; nt < NT; nt++) {
            const __nv_bfloat16* q = Bs + (wn * (NT * 8) + nt * 8 + gid) * SA + k0 + tig * 2;
            bf[nt][0] = *(const unsigned*)(q);
            bf[nt][1] = *(const unsigned*)(q + 8);
        }
#pragma unroll
        for (int mt = 0; mt < 2; mt++)
#pragma unroll
            for (int nt = 0; nt < NT; nt++) {
                asm volatile(
                    "mma.sync.aligned.m16n8k16.row.col.f32.bf16.bf16.f32 "
                    "{%0,%1,%2,%3}, {%4,%5,%6,%7}, {%8,%9}, {%0,%1,%2,%3};"
                    : "+f"(c[mt][nt][0]), "+f"(c[mt][nt][1]),
                      "+f"(c[mt][nt][2]), "+f"(c[mt][nt][3])
                    : "r"(af[mt][0]), "r"(af[mt][1]), "r"(af[mt][2]), "r"(af[mt][3]),
                      "r"(bf[nt][0]), "r"(bf[nt][1]));
            }
    }

    // epilogue: c0,c1 -> (r, col..col+1); c2,c3 -> (r+8, col..col+1)
#pragma unroll
    for (int mt = 0; mt < 2; mt++) {
        int r0 = brow + wm * 32 + mt * 16 + gid;
        int r1 = r0 + 8;
        float p0 = 1.f, p1 = 1.f;
        if (POST) {
            if (r0 < M) p0 = postscale[r0];
            if (r1 < M) p1 = postscale[r1];
        }
#pragma unroll
        for (int nt = 0; nt < NT; nt++) {
            int col = wn * (NT * 8) + nt * 8 + tig * 2;
            float b0v = bs[col], b1v = bs[col + 1];
            float v0 = c[mt][nt][0] + b0v, v1 = c[mt][nt][1] + b1v;
            float v2 = c[mt][nt][2] + b0v, v3 = c[mt][nt][3] + b1v;
            if (MODE == 2) {
                v0 = 1.f / (1.f + __expf(-v0)); v1 = 1.f / (1.f + __expf(-v1));
                v2 = 1.f / (1.f + __expf(-v2)); v3 = 1.f / (1.f + __expf(-v3));
            } else {
                v0 = fmaxf(v0, 0.f) * p0; v1 = fmaxf(v1, 0.f) * p0;
                v2 = fmaxf(v2, 0.f) * p1; v3 = fmaxf(v3, 0.f) * p1;
            }
            if (OUTB) {
                __nv_bfloat16* ob = (__nv_bfloat16*)outp;
                if (r0 < M) {
                    __nv_bfloat162 pk = __floats2bfloat162_rn(v0, v1);
                    *(unsigned*)(ob + (size_t)r0 * NR + col) = *reinterpret_cast<unsigned*>(&pk);
                }
                if (r1 < M) {
                    __nv_bfloat162 pk = __floats2bfloat162_rn(v2, v3);
                    *(unsigned*)(ob + (size_t)r1 * NR + col) = *reinterpret_cast<unsigned*>(&pk);
                }
            } else {
                float* of = (float*)outp;
                if (r0 < M) *(float2*)(of + (size_t)r0 * NR + col) = make_float2(v0, v1);
                if (r1 < M) *(float2*)(of + (size_t)r1 * NR + col) = make_float2(v2, v3);
            }
        }
    }
}

// ---------------- launch ----------------
extern "C" void kernel_launch(void* const* d_in, const int* in_sizes, int n_in,
                              void* d_out, int out_size) {
    const float* x   = (const float*)d_in[0];
    const int*   src = (const int*)d_in[1];
    const int*   dst = (const int*)d_in[2];
    const float* W1  = (const float*)d_in[3];
    const float* b1  = (const float*)d_in[4];
    const float* W2  = (const float*)d_in[5];
    const float* b2  = (const float*)d_in[6];
    const float* Wm1 = (const float*)d_in[7];
    const float* bm1 = (const float*)d_in[8];
    const float* Wm2 = (const float*)d_in[9];
    const float* bm2 = (const float*)d_in[10];
    float* out = (float*)d_out;

    void *p_xb, *p_aggb, *p_hb, *p_mb, *p_w1t, *p_w2t, *p_wm1t, *p_wm2t, *p_outnorm;
    cudaGetSymbolAddress(&p_xb, g_xb);
    cudaGetSymbolAddress(&p_aggb, g_aggb);
    cudaGetSymbolAddress(&p_hb, g_hb);
    cudaGetSymbolAddress(&p_mb, g_mb);
    cudaGetSymbolAddress(&p_w1t, g_w1t);
    cudaGetSymbolAddress(&p_w2t, g_w2t);
    cudaGetSymbolAddress(&p_wm1t, g_wm1t);
    cudaGetSymbolAddress(&p_wm2t, g_wm2t);
    cudaGetSymbolAddress(&p_outnorm, g_outnorm);

    // smem: A 128*136*2 + B NR*136*2 + bias NR*4
    constexpr int SMEM_G128 = 128 * 136 * 2 + 128 * 136 * 2 + 512;  // 70144
    constexpr int SMEM_G64  = 128 * 136 * 2 + 64 * 136 * 2 + 256;   // 52480
    cudaFuncSetAttribute(mma_gemm_kernel<128, 0, true, true>,
                         cudaFuncAttributeMaxDynamicSharedMemorySize, SMEM_G128);
    cudaFuncSetAttribute(mma_gemm_kernel<128, 0, true, false>,
                         cudaFuncAttributeMaxDynamicSharedMemorySize, SMEM_G128);
    cudaFuncSetAttribute(mma_gemm_kernel<64, 2, false, false>,
                         cudaFuncAttributeMaxDynamicSharedMemorySize, SMEM_G64);

    const int TB = 256;
    int eblk = (EE + TB - 1) / TB;
    int sblk = (NN + 1023) / 1024;  // 98
    int gblk = (NN + 127) / 128;    // 782
    int ablk = (NN * 32 + TB - 1) / TB;

    // prep (zero + weights + x->bf16), then graph preprocessing
    prep_kernel<<<ablk, TB>>>((const float4*)x, W1, W2, Wm1, Wm2);
    degree_kernel<<<eblk, TB>>>(src, dst);
    scan_reduce_kernel<<<sblk, 256>>>();
    scan_down_kernel<<<sblk, 1024>>>(sblk);
    fill_kernel<<<eblk, TB>>>(src, dst);

    // conv1
    agg_kernel<true><<<ablk, TB>>>();
    mma_gemm_kernel<128, 0, true, true><<<gblk, 256, SMEM_G128>>>(
        (const __nv_bfloat16*)p_aggb, (const __nv_bfloat16*)p_w1t, b1,
        (const float*)p_outnorm, p_xb, NN);

    // conv2
    agg_kernel<false><<<ablk, TB>>>();
    mma_gemm_kernel<128, 0, true, false><<<gblk, 256, SMEM_G128>>>(
        (const __nv_bfloat16*)p_aggb, (const __nv_bfloat16*)p_w2t, b2,
        nullptr, p_hb, NN);

    // MLP head
    mma_gemm_kernel<128, 0, true, false><<<gblk, 256, SMEM_G128>>>(
        (const __nv_bfloat16*)p_hb, (const __nv_bfloat16*)p_wm1t, bm1,
        nullptr, p_mb, NN);
    mma_gemm_kernel<64, 2, false, false><<<gblk, 256, SMEM_G64>>>(
        (const __nv_bfloat16*)p_mb, (const __nv_bfloat16*)p_wm2t, bm2,
        nullptr, out, NN);
}